// round 2
// baseline (speedup 1.0000x reference)
#include <cuda_runtime.h>
#include <cstdint>
#include <cstddef>

// Problem constants
#define B_TOTAL 32768
#define T_STEPS 30
#define HDIM    384
#define BT      32      // batch rows per CTA
#define NTH     128     // threads per CTA
#define KTOT    512     // K of unified GEMM: [x(128) | hidden(384)]
#define NCOLS   1536    // N of unified GEMM: 384 h * 4 gates (r,z,s,hn)
#define KSLAB   8
#define NSLABS  (KTOT / KSLAB)   // 64
#define NCHUNK  12               // 1536 cols / 128 per chunk
#define D1      64
#define NSLABS2 (HDIM / KSLAB)   // 48

// ---- device scratch (no allocations allowed) ----
__device__ float g_Wpack[KTOT * NCOLS];     // [k][1536], gate-interleaved cols
__device__ float g_bias[NCOLS];
__device__ float g_Wd1T[HDIM * D1];         // [k][64]
__device__ float g_hidden[(size_t)B_TOTAL * HDIM];  // per-step staging

// ----------------------------------------------------------------------------
// Prep: pack W = [W_ih | W_hh] with column order col = 128*chunk + 4*i + g,
// h = 32*chunk + i, gates g: 0=r, 1=z, 2=s (combined inn+hn), 3=hn (zero-pad k<128)
// ----------------------------------------------------------------------------
__global__ void pack_kernel(const float* __restrict__ W_ih,
                            const float* __restrict__ W_hh,
                            const float* __restrict__ b_ih,
                            const float* __restrict__ b_hh,
                            const float* __restrict__ Wd1)
{
    int idx = blockIdx.x * blockDim.x + threadIdx.x;
    if (idx < KTOT * NCOLS) {
        int k = idx / NCOLS;
        int p = idx - k * NCOLS;
        int c = p >> 7;
        int q = p & 127;
        int i = q >> 2;
        int g = q & 3;
        int h = c * 32 + i;
        float v;
        if (g < 3) {
            int row = g * HDIM + h;   // g=2 -> row 768+h (n-gate, combined)
            v = (k < 128) ? W_ih[row * 128 + k] : W_hh[row * HDIM + (k - 128)];
        } else {
            v = (k < 128) ? 0.0f : W_hh[(2 * HDIM + h) * HDIM + (k - 128)];
        }
        g_Wpack[idx] = v;
    }
    if (idx < NCOLS) {
        int c = idx >> 7, q = idx & 127, i = q >> 2, g = q & 3;
        int h = c * 32 + i;
        float bv;
        if (g == 3) bv = b_hh[2 * HDIM + h];
        else        bv = b_ih[g * HDIM + h] + b_hh[g * HDIM + h];
        g_bias[idx] = bv;
    }
    if (idx < HDIM * D1) {
        int k = idx >> 6, j = idx & 63;
        g_Wd1T[idx] = Wd1[j * HDIM + k];
    }
}

// ---- cp.async helpers ----
__device__ __forceinline__ void cp16(float* dst, const float* src) {
    unsigned d = (unsigned)__cvta_generic_to_shared(dst);
    asm volatile("cp.async.ca.shared.global [%0], [%1], 16;\n" :: "r"(d), "l"(src));
}
__device__ __forceinline__ void cp_commit() {
    asm volatile("cp.async.commit_group;\n");
}
template<int N> __device__ __forceinline__ void cp_wait() {
    asm volatile("cp.async.wait_group %0;\n" :: "n"(N));
}

__device__ __forceinline__ float sigmoid_f(float x) {
    return 1.0f / (1.0f + __expf(-x));
}
__device__ __forceinline__ float tanh_f(float x) {
    // numerically safe for |x| large: exp->inf gives 1, exp->0 gives -1
    float e2 = __expf(2.0f * x);
    return 1.0f - 2.0f / (e2 + 1.0f);
}

// ----------------------------------------------------------------------------
// Persistent per-batch-tile decoder: each CTA owns BT=32 rows through T=30 steps
// ----------------------------------------------------------------------------
__global__ void __launch_bounds__(NTH, 3)
decoder_kernel(const float* __restrict__ init_hidden,
               const float* __restrict__ plan,
               const float* __restrict__ gate,
               const float* __restrict__ init_state,
               const float* __restrict__ Wp, const float* __restrict__ bp,
               const float* __restrict__ Ws, const float* __restrict__ bs,
               const float* __restrict__ Wd2, const float* __restrict__ bd2,
               const float* __restrict__ bd1,
               float* __restrict__ out)
{
    extern __shared__ float sm[];
    float* hs     = sm;                       // BT*HDIM = 12288 f
    float* xs     = hs + BT * HDIM;           // BT*128  = 4096 f (reused as d1 buf)
    float* slab   = xs + BT * 128;            // 2*KSLAB*128 = 2048 f
    float* plan_s = slab + 2 * KSLAB * 128;   // 96 f
    float* st_s   = plan_s + 96;              // 96 f
    float* gate_s = st_s + 96;                // 32 f

    const int tid  = threadIdx.x;
    const int lane = tid & 31;
    const int warp = tid >> 5;
    const int b0   = warp * 8;                // each warp owns 8 batch rows
    const int bg0  = blockIdx.x * BT;

    // ---- init ----
    for (int i = tid; i < BT * HDIM; i += NTH)
        hs[i] = init_hidden[(size_t)bg0 * HDIM + i];
    if (tid < BT * 3) st_s[tid] = init_state[bg0 * 3 + tid];
    if (tid < BT)     gate_s[tid] = gate[bg0 + tid];

    // per-thread x-projection params (thread tid owns column j = tid of x)
    const float ws0 = Ws[tid * 3 + 0], ws1 = Ws[tid * 3 + 1], ws2 = Ws[tid * 3 + 2];
    const float wp0 = Wp[tid * 3 + 0], wp1 = Wp[tid * 3 + 1], wp2 = Wp[tid * 3 + 2];
    const float bsj = bs[tid], bpj = bp[tid];
    __syncthreads();

    // slab-copy mapping (main GEMM): thread copies 2 consecutive float4s
    const int f    = tid * 2;
    const int srow = f >> 5;          // 0..7
    const int scol = (f & 31) << 2;   // 0..120 (pairs cover 128 cols)
    // slab-copy mapping (decode GEMM): thread copies 1 float4 of an 8x64 slab
    const int drow = tid >> 4;        // 0..7
    const int dcol = (tid & 15) << 2; // 0..60

    for (int t = 0; t < T_STEPS; ++t) {
        // ---- stage plan_t ----
        if (tid < BT * 3) {
            int b = tid / 3, j = tid - b * 3;
            plan_s[tid] = plan[(size_t)(bg0 + b) * (T_STEPS * 3) + t * 3 + j];
        }
        __syncthreads();

        // ---- x = state@Ws^T + bs + gate*(plan@Wp^T + bp) ----
        #pragma unroll 4
        for (int b = 0; b < BT; ++b) {
            float v = bsj + ws0 * st_s[b * 3] + ws1 * st_s[b * 3 + 1] + ws2 * st_s[b * 3 + 2]
                    + gate_s[b] * (bpj + wp0 * plan_s[b * 3] + wp1 * plan_s[b * 3 + 1]
                                       + wp2 * plan_s[b * 3 + 2]);
            xs[b * 128 + tid] = v;
        }
        __syncthreads();

        // ---- unified gate GEMM: [BT x 512] * [512 x 1536], in 12 col-chunks ----
        for (int c = 0; c < NCHUNK; ++c) {
            const float* wbase = g_Wpack + c * 128;
            float4 bias4 = *reinterpret_cast<const float4*>(&g_bias[c * 128 + (lane << 2)]);
            float acc[8][4];
            #pragma unroll
            for (int r = 0; r < 8; ++r) {
                acc[r][0] = bias4.x; acc[r][1] = bias4.y;
                acc[r][2] = bias4.z; acc[r][3] = bias4.w;
            }

            // prologue: slab 0
            cp16(&slab[srow * 128 + scol],     wbase + (size_t)srow * NCOLS + scol);
            cp16(&slab[srow * 128 + scol + 4], wbase + (size_t)srow * NCOLS + scol + 4);
            cp_commit();

            for (int s = 0; s < NSLABS; ++s) {
                if (s + 1 < NSLABS) {
                    const float* src = wbase + (size_t)(s + 1) * KSLAB * NCOLS;
                    float* dst = slab + ((s + 1) & 1) * (KSLAB * 128);
                    cp16(&dst[srow * 128 + scol],     src + (size_t)srow * NCOLS + scol);
                    cp16(&dst[srow * 128 + scol + 4], src + (size_t)srow * NCOLS + scol + 4);
                    cp_commit();
                    cp_wait<1>();
                } else {
                    cp_wait<0>();
                }
                __syncthreads();

                const float* sl = slab + (s & 1) * (KSLAB * 128);
                const bool in_x = (s < 128 / KSLAB);
                const float* A  = in_x ? (xs + b0 * 128) : (hs + b0 * HDIM);
                const int astride = in_x ? 128 : HDIM;
                const int kb = in_x ? (s * KSLAB) : (s * KSLAB - 128);

                #pragma unroll
                for (int kk = 0; kk < KSLAB; ++kk) {
                    float4 wv = *reinterpret_cast<const float4*>(&sl[kk * 128 + (lane << 2)]);
                    #pragma unroll
                    for (int r = 0; r < 8; ++r) {
                        float a = A[r * astride + kb + kk];   // warp-broadcast LDS
                        acc[r][0] = fmaf(a, wv.x, acc[r][0]);
                        acc[r][1] = fmaf(a, wv.y, acc[r][1]);
                        acc[r][2] = fmaf(a, wv.z, acc[r][2]);
                        acc[r][3] = fmaf(a, wv.w, acc[r][3]);
                    }
                }
                __syncthreads();
            }

            // ---- GRU pointwise for h = c*32 + lane, 8 rows ----
            const int h = c * 32 + lane;
            #pragma unroll
            for (int r = 0; r < 8; ++r) {
                float oldh = hs[(b0 + r) * HDIM + h];
                float rg = sigmoid_f(acc[r][0]);
                float zg = sigmoid_f(acc[r][1]);
                // s-col = inn+hn (both biases), hn-col = hn (b_hh bias):
                // n_pre = inn + r*hn = s + (r-1)*hn
                float ng = tanh_f(acc[r][2] + (rg - 1.0f) * acc[r][3]);
                float nh = (1.0f - zg) * ng + zg * oldh;
                g_hidden[(size_t)(bg0 + b0 + r) * HDIM + h] = nh;   // stage new hidden
            }
        }
        __syncthreads();

        // ---- pull new hidden back into smem (old hs no longer needed) ----
        for (int i = tid; i < BT * HDIM; i += NTH)
            hs[i] = g_hidden[(size_t)bg0 * HDIM + i];
        __syncthreads();

        // ---- decode layer 1: d1 = elu(hidden @ Wd1^T + bd1), [BT x 64], K=384 ----
        {
            float acc2[8][2];
            const float bb0 = bd1[lane * 2], bb1 = bd1[lane * 2 + 1];
            #pragma unroll
            for (int r = 0; r < 8; ++r) { acc2[r][0] = bb0; acc2[r][1] = bb1; }

            cp16(&slab[drow * 64 + dcol], g_Wd1T + (size_t)drow * D1 + dcol);
            cp_commit();

            for (int s = 0; s < NSLABS2; ++s) {
                if (s + 1 < NSLABS2) {
                    float* dst = slab + ((s + 1) & 1) * (KSLAB * 128);
                    cp16(&dst[drow * 64 + dcol],
                         g_Wd1T + (size_t)((s + 1) * KSLAB + drow) * D1 + dcol);
                    cp_commit();
                    cp_wait<1>();
                } else {
                    cp_wait<0>();
                }
                __syncthreads();
                const float* sl = slab + (s & 1) * (KSLAB * 128);
                #pragma unroll
                for (int kk = 0; kk < KSLAB; ++kk) {
                    float2 wv = *reinterpret_cast<const float2*>(&sl[kk * 64 + (lane << 1)]);
                    #pragma unroll
                    for (int r = 0; r < 8; ++r) {
                        float a = hs[(b0 + r) * HDIM + s * KSLAB + kk];
                        acc2[r][0] = fmaf(a, wv.x, acc2[r][0]);
                        acc2[r][1] = fmaf(a, wv.y, acc2[r][1]);
                    }
                }
                __syncthreads();
            }

            // ELU, store d1 into xs region (free until next step's x)
            #pragma unroll
            for (int r = 0; r < 8; ++r) {
                float v0 = acc2[r][0], v1 = acc2[r][1];
                v0 = v0 > 0.0f ? v0 : (__expf(v0) - 1.0f);
                v1 = v1 > 0.0f ? v1 : (__expf(v1) - 1.0f);
                xs[(b0 + r) * 64 + lane * 2]     = v0;
                xs[(b0 + r) * 64 + lane * 2 + 1] = v1;
            }
        }
        __syncthreads();

        // ---- decode layer 2 + state update + output write ----
        if (tid < BT * 3) {
            int b = tid / 3, j = tid - b * 3;
            const float* w = Wd2 + j * 64;
            const float* d = xs + b * 64;
            float sum = bd2[j];
            #pragma unroll
            for (int k = 0; k < 64; ++k)
                sum = fmaf(d[k], __ldg(&w[k]), sum);
            float ns = st_s[tid] + sum;
            st_s[tid] = ns;
            out[(size_t)(bg0 + b) * (T_STEPS * 3) + t * 3 + j] = ns;
        }
        __syncthreads();
    }
}

// ----------------------------------------------------------------------------
extern "C" void kernel_launch(void* const* d_in, const int* in_sizes, int n_in,
                              void* d_out, int out_size)
{
    (void)in_sizes; (void)n_in; (void)out_size;
    const float* init_hidden = (const float*)d_in[0];
    const float* plan        = (const float*)d_in[1];
    const float* gate        = (const float*)d_in[2];
    const float* init_state  = (const float*)d_in[3];
    const float* Wp   = (const float*)d_in[4];
    const float* bp   = (const float*)d_in[5];
    const float* Ws   = (const float*)d_in[6];
    const float* bs   = (const float*)d_in[7];
    const float* W_ih = (const float*)d_in[8];
    const float* b_ih = (const float*)d_in[9];
    const float* W_hh = (const float*)d_in[10];
    const float* b_hh = (const float*)d_in[11];
    const float* Wd1  = (const float*)d_in[12];
    const float* bd1  = (const float*)d_in[13];
    const float* Wd2  = (const float*)d_in[14];
    const float* bd2  = (const float*)d_in[15];
    float* out = (float*)d_out;

    pack_kernel<<<(KTOT * NCOLS + 255) / 256, 256>>>(W_ih, W_hh, b_ih, b_hh, Wd1);

    const int smem_bytes = (BT * HDIM + BT * 128 + 2 * KSLAB * 128 + 96 + 96 + 32) * 4;
    cudaFuncSetAttribute(decoder_kernel,
                         cudaFuncAttributeMaxDynamicSharedMemorySize, smem_bytes);
    decoder_kernel<<<B_TOTAL / BT, NTH, smem_bytes>>>(
        init_hidden, plan, gate, init_state,
        Wp, bp, Ws, bs, Wd2, bd2, bd1, out);
}